// round 3
// baseline (speedup 1.0000x reference)
#include <cuda_runtime.h>

#define TOTAL_OPS 102400
#define ND 1024
#define NW 64
#define E 256
#define H1N 32
#define H2N 16

// ---------------- device scratch (no allocations allowed) ----------------
__device__ float    g_logits[TOTAL_OPS];
__device__ int      g_dagid[TOTAL_OPS];
__device__ float    g_yw_op[ND * H1N];
__device__ float    g_yw_pr[ND * H1N];
__device__ unsigned g_maxbits;
__device__ float    g_maxf;
__device__ float    g_invsum;

typedef unsigned long long ull;

// ---------------- packed fp32x2 helpers (sm_103a FFMA2 path) ----------------
__device__ __forceinline__ ull fma2(ull a, ull b, ull c) {
    ull d;
    asm("fma.rn.f32x2 %0, %1, %2, %3;" : "=l"(d) : "l"(a), "l"(b), "l"(c));
    return d;
}
__device__ __forceinline__ ull splat2(float x) {
    ull d;
    asm("mov.b64 %0, {%1, %1};" : "=l"(d) : "f"(x));
    return d;
}
__device__ __forceinline__ void unpack2(ull v, float& lo, float& hi) {
    asm("mov.b64 {%0, %1}, %2;" : "=f"(lo), "=f"(hi) : "l"(v));
}

// monotone float -> unsigned map for atomicMax
__device__ __forceinline__ unsigned encf(float f) {
    unsigned b = __float_as_uint(f);
    return (b & 0x80000000u) ? ~b : (b | 0x80000000u);
}
__device__ __forceinline__ float decf(unsigned u) {
    return (u & 0x80000000u) ? __uint_as_float(u & 0x7FFFFFFFu)
                             : __uint_as_float(~u);
}

// ---------------- K0: dag-id table via scan of num_ops ----------------
__global__ void k_scan(const int* __restrict__ num_ops) {
    __shared__ int s[ND];
    int t = threadIdx.x;
    // prefill with last dag (repeat pads with last value)
    for (int i = t; i < TOTAL_OPS; i += ND) g_dagid[i] = ND - 1;
    int cnt = num_ops[t];
    s[t] = cnt;
    __syncthreads();
    for (int off = 1; off < ND; off <<= 1) {
        int v = (t >= off) ? s[t - off] : 0;
        __syncthreads();
        s[t] += v;
        __syncthreads();
    }
    int start = s[t] - cnt;
    for (int i = 0; i < cnt; i++) {
        int p = start + i;
        if (p < TOTAL_OPS) g_dagid[p] = t;
    }
    if (t == 0) { g_maxbits = 0u; }
}

// ---------------- K1: precompute yW tables (y@W1y + z@W1z + b1) ----------------
__global__ void __launch_bounds__(256) k_pre(
    const float* __restrict__ opW1, const float* __restrict__ opb1,
    const float* __restrict__ prW1, const float* __restrict__ prb1,
    const float* __restrict__ y, const float* __restrict__ z)
{
    int which = blockIdx.x >> 2;            // 0: op table, 1: pr table
    int d0 = (blockIdx.x & 3) * 256;
    const float* W1 = which ? prW1 : opW1;
    const float* b1 = which ? prb1 : opb1;
    int offY = which ? 1 : E;               // row offset of y-part in W1
    int offZ = which ? (E + 1) : (2 * E);   // row offset of z-part
    float* outT = which ? g_yw_pr : g_yw_op;

    __shared__ __align__(16) float sW[E * H1N];   // 32KB: y-part of W1
    __shared__ float cvec[H1N];
    int t = threadIdx.x;
    for (int i = t; i < E * H1N; i += 256) sW[i] = W1[offY * H1N + i];
    if (t < H1N) {
        float c = b1[t];
        for (int k = 0; k < E; k++) c += z[k] * W1[(offZ + k) * H1N + t];
        cvec[t] = c;
    }
    __syncthreads();

    int d = d0 + t;                          // one dag per thread
    float acc[H1N];
#pragma unroll
    for (int j = 0; j < H1N; j++) acc[j] = 0.f;
    const float* yr = &y[d * E];
    for (int k = 0; k < E; k++) {
        float yv = yr[k];
        const float4* w = (const float4*)&sW[k * H1N];
#pragma unroll
        for (int q = 0; q < 8; q++) {
            float4 wv = w[q];
            acc[4 * q + 0] += yv * wv.x;
            acc[4 * q + 1] += yv * wv.y;
            acc[4 * q + 2] += yv * wv.z;
            acc[4 * q + 3] += yv * wv.w;
        }
    }
#pragma unroll
    for (int j = 0; j < H1N; j++) outT[d * H1N + j] = acc[j] + cvec[j];
}

// ---------------- K2: op MLP -> logits + block max ----------------
__global__ void __launch_bounds__(128) k_ops(
    const float* __restrict__ x, const float* __restrict__ opW1,
    const float* __restrict__ opW2, const float* __restrict__ opb2,
    const float* __restrict__ opW3, const float* __restrict__ opb3,
    const float* __restrict__ op_msk, int nrows)
{
    __shared__ float4 sW4[E * 8];                    // 32KB W1 x-part (rows 0..255)
    __shared__ float sX[128 * 17];                   // x tile, pad-17 conflict-free
    __shared__ __align__(16) float sW2[H1N * H2N];
    __shared__ float sb2[H2N], sW3[H2N];
    __shared__ float sb3;
    __shared__ float wmax[4];

    int t = threadIdx.x;
    const float4* gW4 = (const float4*)opW1;         // first 2048 float4 = x-part
#pragma unroll
    for (int i = 0; i < 16; i++) sW4[i * 128 + t] = gW4[i * 128 + t];
    for (int i = t; i < H1N * H2N; i += 128) sW2[i] = opW2[i];
    if (t < H2N) { sb2[t] = opb2[t]; sW3[t] = opW3[t]; }
    if (t == 0) sb3 = opb3[0];

    int row0 = blockIdx.x * 128;
    ull acc[16];
#pragma unroll
    for (int j = 0; j < 16; j++) acc[j] = 0ull;
    const ulonglong2* sWu = (const ulonglong2*)sW4;

    for (int kc = 0; kc < 16; kc++) {
        __syncthreads();
#pragma unroll
        for (int i = 0; i < 4; i++) {                // stage 128 rows x 16 cols
            int f4 = i * 128 + t;
            int r = f4 >> 2, c4 = f4 & 3;
            int grow = row0 + r;
            float4 v = make_float4(0.f, 0.f, 0.f, 0.f);
            if (grow < nrows) v = *(const float4*)&x[grow * E + kc * 16 + c4 * 4];
            float* dst = &sX[r * 17 + c4 * 4];
            dst[0] = v.x; dst[1] = v.y; dst[2] = v.z; dst[3] = v.w;
        }
        __syncthreads();
#pragma unroll
        for (int kk = 0; kk < 16; kk++) {
            float xv = sX[t * 17 + kk];
            ull xd = splat2(xv);
            int kb = (kc * 16 + kk) * 8;
#pragma unroll
            for (int q = 0; q < 8; q++) {
                ulonglong2 wv = sWu[kb + q];         // broadcast LDS.128
                acc[2 * q]     = fma2(xd, wv.x, acc[2 * q]);
                acc[2 * q + 1] = fma2(xd, wv.y, acc[2 * q + 1]);
            }
        }
    }

    int i = row0 + t;
    float logit = -3.402823466e38f;
    if (i < nrows) {
        float h1[H1N];
#pragma unroll
        for (int jp = 0; jp < 16; jp++) unpack2(acc[jp], h1[2 * jp], h1[2 * jp + 1]);
        int dag = g_dagid[i];
        const float4* bw = (const float4*)&g_yw_op[dag * H1N];   // L2-resident
#pragma unroll
        for (int q = 0; q < 8; q++) {
            float4 b = bw[q];
            h1[4 * q + 0] = fmaxf(h1[4 * q + 0] + b.x, 0.f);
            h1[4 * q + 1] = fmaxf(h1[4 * q + 1] + b.y, 0.f);
            h1[4 * q + 2] = fmaxf(h1[4 * q + 2] + b.z, 0.f);
            h1[4 * q + 3] = fmaxf(h1[4 * q + 3] + b.w, 0.f);
        }
        float h2[H2N];
#pragma unroll
        for (int j2 = 0; j2 < H2N; j2++) h2[j2] = sb2[j2];
#pragma unroll
        for (int j = 0; j < H1N; j++) {
            float v = h1[j];
            const float4* w2 = (const float4*)&sW2[j * H2N];
#pragma unroll
            for (int q2 = 0; q2 < 4; q2++) {
                float4 wv = w2[q2];
                h2[4 * q2 + 0] += v * wv.x;
                h2[4 * q2 + 1] += v * wv.y;
                h2[4 * q2 + 2] += v * wv.z;
                h2[4 * q2 + 3] += v * wv.w;
            }
        }
        logit = sb3;
#pragma unroll
        for (int j2 = 0; j2 < H2N; j2++) logit += fmaxf(h2[j2], 0.f) * sW3[j2];
        logit -= (1.f - op_msk[i]) * 1000.f;
        g_logits[i] = logit;
    }
    // block max -> global atomic (one per block)
    float m = logit;
#pragma unroll
    for (int o = 16; o > 0; o >>= 1) m = fmaxf(m, __shfl_xor_sync(0xffffffffu, m, o));
    if ((t & 31) == 0) wmax[t >> 5] = m;
    __syncthreads();
    if (t == 0) {
        float bm = fmaxf(fmaxf(wmax[0], wmax[1]), fmaxf(wmax[2], wmax[3]));
        atomicMax(&g_maxbits, encf(bm));
    }
}

// ---------------- K3: global sum of exp ----------------
__global__ void k_reduce(int n) {
    __shared__ float sp[32];
    int t = threadIdx.x;
    float gm = decf(g_maxbits);
    float s = 0.f;
    for (int i = t; i < n; i += 1024) s += expf(g_logits[i] - gm);
#pragma unroll
    for (int o = 16; o > 0; o >>= 1) s += __shfl_xor_sync(0xffffffffu, s, o);
    if ((t & 31) == 0) sp[t >> 5] = s;
    __syncthreads();
    if (t < 32) {
        float v = sp[t];
#pragma unroll
        for (int o = 16; o > 0; o >>= 1) v += __shfl_xor_sync(0xffffffffu, v, o);
        if (t == 0) { g_maxf = gm; g_invsum = 1.f / v; }
    }
}

// ---------------- K4: normalize ops softmax ----------------
__global__ void k_norm(float* __restrict__ out, int n) {
    int i = blockIdx.x * blockDim.x + threadIdx.x;
    if (i < n) out[i] = expf(g_logits[i] - g_maxf) * g_invsum;
}

// ---------------- K5: prlvl branch, fused per-dag softmax ----------------
__global__ void __launch_bounds__(NW) k_prlvl(
    const float* __restrict__ prW1, const float* __restrict__ prW2,
    const float* __restrict__ prb2, const float* __restrict__ prW3,
    const float* __restrict__ prb3, const float* __restrict__ msk,
    float* __restrict__ out)
{
    __shared__ __align__(16) float sW2[H1N * H2N];
    __shared__ float sb2[H2N], sW3[H2N];
    __shared__ float sb3;
    __shared__ float sw1r0[H1N], sbase[H1N];
    __shared__ float sv[NW];

    int d = blockIdx.x, w = threadIdx.x;
    for (int i = w; i < H1N * H2N; i += NW) sW2[i] = prW2[i];
    if (w < H2N) { sb2[w] = prb2[w]; sW3[w] = prW3[w]; }
    if (w == 0) sb3 = prb3[0];
    if (w < H1N) { sw1r0[w] = prW1[w]; sbase[w] = g_yw_pr[d * H1N + w]; }
    __syncthreads();

    float limit = (float)(w + 1);
    float h2[H2N];
#pragma unroll
    for (int j2 = 0; j2 < H2N; j2++) h2[j2] = sb2[j2];
#pragma unroll
    for (int j = 0; j < H1N; j++) {
        float v = fmaxf(sbase[j] + limit * sw1r0[j], 0.f);
        const float4* w2 = (const float4*)&sW2[j * H2N];
#pragma unroll
        for (int q2 = 0; q2 < 4; q2++) {
            float4 wv = w2[q2];
            h2[4 * q2 + 0] += v * wv.x;
            h2[4 * q2 + 1] += v * wv.y;
            h2[4 * q2 + 2] += v * wv.z;
            h2[4 * q2 + 3] += v * wv.w;
        }
    }
    float logit = sb3;
#pragma unroll
    for (int j2 = 0; j2 < H2N; j2++) logit += fmaxf(h2[j2], 0.f) * sW3[j2];
    logit -= (1.f - msk[d * NW + w]) * 1000.f;

    sv[w] = logit;
    __syncthreads();
    float m = -3.402823466e38f;
#pragma unroll
    for (int i = 0; i < NW; i++) m = fmaxf(m, sv[i]);
    float e = expf(logit - m);
    __syncthreads();
    sv[w] = e;
    __syncthreads();
    float s = 0.f;
#pragma unroll
    for (int i = 0; i < NW; i++) s += sv[i];
    out[TOTAL_OPS + d * NW + w] = e / s;
}

// ---------------- launcher ----------------
extern "C" void kernel_launch(void* const* d_in, const int* in_sizes, int n_in,
                              void* d_out, int out_size) {
    // If num_dags/num_workers scalars are present as inputs, n_in == 20 and
    // tensors shift by 2; otherwise n_in == 18.
    int o = (n_in >= 20) ? 2 : 0;
    const int*   num_ops = (const int*)d_in[0];
    const float* x       = (const float*)d_in[1 + o];
    const float* y       = (const float*)d_in[2 + o];
    const float* z       = (const float*)d_in[3 + o];
    const float* op_msk  = (const float*)d_in[4 + o];
    const float* pr_msk  = (const float*)d_in[5 + o];
    const float* opW1    = (const float*)d_in[6 + o];
    const float* opb1    = (const float*)d_in[7 + o];
    const float* opW2    = (const float*)d_in[8 + o];
    const float* opb2    = (const float*)d_in[9 + o];
    const float* opW3    = (const float*)d_in[10 + o];
    const float* opb3    = (const float*)d_in[11 + o];
    const float* prW1    = (const float*)d_in[12 + o];
    const float* prb1    = (const float*)d_in[13 + o];
    const float* prW2    = (const float*)d_in[14 + o];
    const float* prb2    = (const float*)d_in[15 + o];
    const float* prW3    = (const float*)d_in[16 + o];
    const float* prb3    = (const float*)d_in[17 + o];
    float* out = (float*)d_out;

    int n = in_sizes[1 + o] / E;   // total ops (102400)

    k_scan<<<1, ND>>>(num_ops);
    k_pre<<<8, 256>>>(opW1, opb1, prW1, prb1, y, z);
    k_ops<<<(n + 127) / 128, 128>>>(x, opW1, opW2, opb2, opW3, opb3, op_msk, n);
    k_reduce<<<1, 1024>>>(n);
    k_norm<<<(n + 1023) / 1024, 1024>>>(out, n);
    k_prlvl<<<ND, NW>>>(prW1, prW2, prb2, prW3, prb3, pr_msk, out);
}

// round 4
// speedup vs baseline: 2.1068x; 2.1068x over previous
#include <cuda_runtime.h>

#define TOTAL_OPS 102400
#define ND 1024
#define NW 64
#define E 256
#define H1N 32
#define H2N 16

// ---------------- device scratch (no allocations allowed) ----------------
__device__ float    g_logits[TOTAL_OPS];
__device__ int      g_cum[ND];          // inclusive cumsum of num_ops
__device__ float    g_yw_op[ND * H1N];
__device__ float    g_yw_pr[ND * H1N];
__device__ float    g_zc_op[H1N];       // b1 + z@W1z (op)
__device__ float    g_zc_pr[H1N];       // b1 + z@W1z (pr)
__device__ unsigned g_maxbits;
__device__ float    g_sum;

typedef unsigned long long ull;

// ---------------- packed fp32x2 helpers (sm_103a FFMA2 path) ----------------
__device__ __forceinline__ ull fma2(ull a, ull b, ull c) {
    ull d;
    asm("fma.rn.f32x2 %0, %1, %2, %3;" : "=l"(d) : "l"(a), "l"(b), "l"(c));
    return d;
}
__device__ __forceinline__ ull splat2(float x) {
    ull d;
    asm("mov.b64 %0, {%1, %1};" : "=l"(d) : "f"(x));
    return d;
}
__device__ __forceinline__ void unpack2(ull v, float& lo, float& hi) {
    asm("mov.b64 {%0, %1}, %2;" : "=f"(lo), "=f"(hi) : "l"(v));
}

// monotone float -> unsigned map for atomicMax
__device__ __forceinline__ unsigned encf(float f) {
    unsigned b = __float_as_uint(f);
    return (b & 0x80000000u) ? ~b : (b | 0x80000000u);
}
__device__ __forceinline__ float decf(unsigned u) {
    return (u & 0x80000000u) ? __uint_as_float(u & 0x7FFFFFFFu)
                             : __uint_as_float(~u);
}

// ---------------- K0: scan + z-projections + resets (1 block) ----------------
__global__ void __launch_bounds__(1024) k_setup(
    const int* __restrict__ num_ops,
    const float* __restrict__ z,
    const float* __restrict__ opW1, const float* __restrict__ opb1,
    const float* __restrict__ prW1, const float* __restrict__ prb1)
{
    __shared__ int s[ND];
    int t = threadIdx.x;

    // --- inclusive scan of num_ops (1024 wide) ---
    s[t] = num_ops[t];
    __syncthreads();
    for (int off = 1; off < ND; off <<= 1) {
        int v = (t >= off) ? s[t - off] : 0;
        __syncthreads();
        s[t] += v;
        __syncthreads();
    }
    g_cum[t] = s[t];

    // --- z-projections: 64 outputs x 16 threads x 16 k-terms ---
    int table = t >> 9;                 // 0 = op, 1 = pr
    int j     = (t >> 4) & 31;          // output index
    int sub   = t & 15;                 // k sub-chunk
    const float* W1 = table ? prW1 : opW1;
    const float* b1 = table ? prb1 : opb1;
    int offZ = table ? (E + 1) : (2 * E);
    float c = 0.f;
    int k0 = sub * 16;
#pragma unroll 4
    for (int k = k0; k < k0 + 16; k++)
        c += z[k] * W1[(offZ + k) * H1N + j];
#pragma unroll
    for (int o = 8; o > 0; o >>= 1)
        c += __shfl_xor_sync(0xffffffffu, c, o);   // within 16-lane group
    if (sub == 0) {
        float v = c + b1[j];
        if (table) g_zc_pr[j] = v; else g_zc_op[j] = v;
    }

    if (t == 0) { g_maxbits = 0u; g_sum = 0.f; }
}

// ---------------- K1: per-dag tables yW = y@W1y + zc ----------------
__global__ void __launch_bounds__(128) k_pre(
    const float* __restrict__ opW1, const float* __restrict__ prW1,
    const float* __restrict__ y)
{
    __shared__ __align__(16) float sW[E * H1N];    // 32 KB y-part of W1
    __shared__ float szc[H1N];
    int b = blockIdx.x;
    int table = b >> 3;                 // blocks 0-7 op, 8-15 pr
    int d0 = (b & 7) * 128;
    const float* W1 = table ? prW1 : opW1;
    int f4off = table ? (1 * H1N / 4) : (E * H1N / 4);   // float4 offset of y-part
    const float* zc = table ? g_zc_pr : g_zc_op;
    float* outT = table ? g_yw_pr : g_yw_op;

    int t = threadIdx.x;
    const float4* gW4 = (const float4*)W1;
    float4* sW4 = (float4*)sW;
#pragma unroll
    for (int i = 0; i < 16; i++) sW4[i * 128 + t] = gW4[f4off + i * 128 + t];
    if (t < H1N) szc[t] = zc[t];
    __syncthreads();

    int d = d0 + t;
    ull acc[16];
#pragma unroll
    for (int q = 0; q < 16; q++) acc[q] = 0ull;
    const float4* yr = (const float4*)&y[d * E];
    const ulonglong2* sWu = (const ulonglong2*)sW;

    for (int kc = 0; kc < 64; kc++) {
        float4 v = yr[kc];
        float f[4] = {v.x, v.y, v.z, v.w};
#pragma unroll
        for (int kk = 0; kk < 4; kk++) {
            ull xd = splat2(f[kk]);
            const ulonglong2* w = &sWu[(kc * 4 + kk) * 8];
#pragma unroll
            for (int q = 0; q < 8; q++) {
                ulonglong2 wv = w[q];
                acc[2 * q]     = fma2(xd, wv.x, acc[2 * q]);
                acc[2 * q + 1] = fma2(xd, wv.y, acc[2 * q + 1]);
            }
        }
    }
    float h[H1N];
#pragma unroll
    for (int q = 0; q < 16; q++) unpack2(acc[q], h[2 * q], h[2 * q + 1]);
#pragma unroll
    for (int j = 0; j < H1N; j++) outT[d * H1N + j] = h[j] + szc[j];
}

// ---------------- K2: op MLP -> logits + block max (2 rows/thread) -----------
__global__ void __launch_bounds__(128) k_ops(
    const float* __restrict__ x, const float* __restrict__ opW1,
    const float* __restrict__ opW2, const float* __restrict__ opb2,
    const float* __restrict__ opW3, const float* __restrict__ opb3,
    const float* __restrict__ op_msk, int nrows)
{
    __shared__ __align__(16) float sW[E * H1N];    // 32 KB W1 x-part
    __shared__ int sCum[ND];                       // 4 KB cumsum
    __shared__ __align__(16) float sW2[H1N * H2N];
    __shared__ float sb2[H2N], sW3[H2N];
    __shared__ float sb3;
    __shared__ float wmax[4];

    int t = threadIdx.x;
    const float4* gW4 = (const float4*)opW1;       // rows 0..255 = x-part
    float4* sW4 = (float4*)sW;
#pragma unroll
    for (int i = 0; i < 16; i++) sW4[i * 128 + t] = gW4[i * 128 + t];
#pragma unroll
    for (int i = 0; i < 8; i++) sCum[i * 128 + t] = g_cum[i * 128 + t];
    for (int i = t; i < H1N * H2N; i += 128) sW2[i] = opW2[i];
    if (t < H2N) { sb2[t] = opb2[t]; sW3[t] = opW3[t]; }
    if (t == 0) sb3 = opb3[0];
    __syncthreads();

    int row0 = blockIdx.x * 256;
    int ia = row0 + t, ib = row0 + 128 + t;
    const float4* xa = (const float4*)&x[(size_t)min(ia, nrows - 1) * E];
    const float4* xb = (const float4*)&x[(size_t)min(ib, nrows - 1) * E];

    ull accA[16], accB[16];
#pragma unroll
    for (int q = 0; q < 16; q++) { accA[q] = 0ull; accB[q] = 0ull; }
    const ulonglong2* sWu = (const ulonglong2*)sW;

    for (int kc = 0; kc < 64; kc++) {
        float4 va = xa[kc];
        float4 vb = xb[kc];
        float fa[4] = {va.x, va.y, va.z, va.w};
        float fb[4] = {vb.x, vb.y, vb.z, vb.w};
#pragma unroll
        for (int kk = 0; kk < 4; kk++) {
            ull da = splat2(fa[kk]);
            ull db = splat2(fb[kk]);
            const ulonglong2* w = &sWu[(kc * 4 + kk) * 8];
#pragma unroll
            for (int q = 0; q < 8; q++) {
                ulonglong2 wv = w[q];
                accA[2 * q]     = fma2(da, wv.x, accA[2 * q]);
                accA[2 * q + 1] = fma2(da, wv.y, accA[2 * q + 1]);
                accB[2 * q]     = fma2(db, wv.x, accB[2 * q]);
                accB[2 * q + 1] = fma2(db, wv.y, accB[2 * q + 1]);
            }
        }
    }

    float m = -3.402823466e38f;
#pragma unroll
    for (int r = 0; r < 2; r++) {
        int i = r ? ib : ia;
        ull* acc = r ? accB : accA;
        if (i < nrows) {
            float h1[H1N];
#pragma unroll
            for (int q = 0; q < 16; q++) unpack2(acc[q], h1[2 * q], h1[2 * q + 1]);
            // dag = max{ d : exclusive_cum[d] <= i }
            int d = 0;
#pragma unroll
            for (int s = 512; s > 0; s >>= 1)
                if (d + s <= ND - 1 && sCum[d + s - 1] <= i) d += s;
            const float4* bw = (const float4*)&g_yw_op[d * H1N];
#pragma unroll
            for (int q = 0; q < 8; q++) {
                float4 b = bw[q];
                h1[4 * q + 0] = fmaxf(h1[4 * q + 0] + b.x, 0.f);
                h1[4 * q + 1] = fmaxf(h1[4 * q + 1] + b.y, 0.f);
                h1[4 * q + 2] = fmaxf(h1[4 * q + 2] + b.z, 0.f);
                h1[4 * q + 3] = fmaxf(h1[4 * q + 3] + b.w, 0.f);
            }
            float h2[H2N];
#pragma unroll
            for (int j2 = 0; j2 < H2N; j2++) h2[j2] = sb2[j2];
#pragma unroll
            for (int j = 0; j < H1N; j++) {
                float v = h1[j];
                const float4* w2 = (const float4*)&sW2[j * H2N];
#pragma unroll
                for (int q2 = 0; q2 < 4; q2++) {
                    float4 wv = w2[q2];
                    h2[4 * q2 + 0] += v * wv.x;
                    h2[4 * q2 + 1] += v * wv.y;
                    h2[4 * q2 + 2] += v * wv.z;
                    h2[4 * q2 + 3] += v * wv.w;
                }
            }
            float logit = sb3;
#pragma unroll
            for (int j2 = 0; j2 < H2N; j2++) logit += fmaxf(h2[j2], 0.f) * sW3[j2];
            logit -= (1.f - op_msk[i]) * 1000.f;
            g_logits[i] = logit;
            m = fmaxf(m, logit);
        }
    }
    // block max -> one global atomic
#pragma unroll
    for (int o = 16; o > 0; o >>= 1) m = fmaxf(m, __shfl_xor_sync(0xffffffffu, m, o));
    if ((t & 31) == 0) wmax[t >> 5] = m;
    __syncthreads();
    if (t == 0) {
        float bm = fmaxf(fmaxf(wmax[0], wmax[1]), fmaxf(wmax[2], wmax[3]));
        atomicMax(&g_maxbits, encf(bm));
    }
}

// ---------------- K3: exp in place + global sum (full chip) ----------------
__global__ void __launch_bounds__(256) k_sum(int n) {
    __shared__ float sp[8];
    int t = threadIdx.x;
    float gm = decf(g_maxbits);
    float s = 0.f;
    for (int i = blockIdx.x * 256 + t; i < n; i += gridDim.x * 256) {
        float e = expf(g_logits[i] - gm);
        g_logits[i] = e;
        s += e;
    }
#pragma unroll
    for (int o = 16; o > 0; o >>= 1) s += __shfl_xor_sync(0xffffffffu, s, o);
    if ((t & 31) == 0) sp[t >> 5] = s;
    __syncthreads();
    if (t == 0) {
        float bs = 0.f;
#pragma unroll
        for (int w = 0; w < 8; w++) bs += sp[w];
        atomicAdd(&g_sum, bs);
    }
}

// ---------------- K4: normalize ----------------
__global__ void __launch_bounds__(1024) k_norm(float* __restrict__ out, int n) {
    int i = blockIdx.x * 1024 + threadIdx.x;
    if (i < n) out[i] = g_logits[i] * (1.f / g_sum);
}

// ---------------- K5: prlvl branch, fused per-dag softmax ----------------
__global__ void __launch_bounds__(NW) k_prlvl(
    const float* __restrict__ prW1, const float* __restrict__ prW2,
    const float* __restrict__ prb2, const float* __restrict__ prW3,
    const float* __restrict__ prb3, const float* __restrict__ msk,
    float* __restrict__ out, int nops)
{
    __shared__ __align__(16) float sW2[H1N * H2N];
    __shared__ float sb2[H2N], sW3[H2N];
    __shared__ float sb3;
    __shared__ float sw1r0[H1N], sbase[H1N];
    __shared__ float red[2];

    int d = blockIdx.x, w = threadIdx.x;
    for (int i = w; i < H1N * H2N; i += NW) sW2[i] = prW2[i];
    if (w < H2N) { sb2[w] = prb2[w]; sW3[w] = prW3[w]; }
    if (w == 0) sb3 = prb3[0];
    if (w < H1N) { sw1r0[w] = prW1[w]; sbase[w] = g_yw_pr[d * H1N + w]; }
    __syncthreads();

    float limit = (float)(w + 1);
    float h2[H2N];
#pragma unroll
    for (int j2 = 0; j2 < H2N; j2++) h2[j2] = sb2[j2];
#pragma unroll
    for (int j = 0; j < H1N; j++) {
        float v = fmaxf(sbase[j] + limit * sw1r0[j], 0.f);
        const float4* w2 = (const float4*)&sW2[j * H2N];
#pragma unroll
        for (int q2 = 0; q2 < 4; q2++) {
            float4 wv = w2[q2];
            h2[4 * q2 + 0] += v * wv.x;
            h2[4 * q2 + 1] += v * wv.y;
            h2[4 * q2 + 2] += v * wv.z;
            h2[4 * q2 + 3] += v * wv.w;
        }
    }
    float logit = sb3;
#pragma unroll
    for (int j2 = 0; j2 < H2N; j2++) logit += fmaxf(h2[j2], 0.f) * sW3[j2];
    logit -= (1.f - msk[d * NW + w]) * 1000.f;

    // 2-warp max
    float m = logit;
#pragma unroll
    for (int o = 16; o > 0; o >>= 1) m = fmaxf(m, __shfl_xor_sync(0xffffffffu, m, o));
    if ((w & 31) == 0) red[w >> 5] = m;
    __syncthreads();
    m = fmaxf(red[0], red[1]);
    float e = expf(logit - m);
    // 2-warp sum
    float s = e;
#pragma unroll
    for (int o = 16; o > 0; o >>= 1) s += __shfl_xor_sync(0xffffffffu, s, o);
    __syncthreads();
    if ((w & 31) == 0) red[w >> 5] = s;
    __syncthreads();
    s = red[0] + red[1];
    out[nops + d * NW + w] = e / s;
}

// ---------------- launcher ----------------
extern "C" void kernel_launch(void* const* d_in, const int* in_sizes, int n_in,
                              void* d_out, int out_size) {
    int o = (n_in >= 20) ? 2 : 0;
    const int*   num_ops = (const int*)d_in[0];
    const float* x       = (const float*)d_in[1 + o];
    const float* y       = (const float*)d_in[2 + o];
    const float* z       = (const float*)d_in[3 + o];
    const float* op_msk  = (const float*)d_in[4 + o];
    const float* pr_msk  = (const float*)d_in[5 + o];
    const float* opW1    = (const float*)d_in[6 + o];
    const float* opb1    = (const float*)d_in[7 + o];
    const float* opW2    = (const float*)d_in[8 + o];
    const float* opb2    = (const float*)d_in[9 + o];
    const float* opW3    = (const float*)d_in[10 + o];
    const float* opb3    = (const float*)d_in[11 + o];
    const float* prW1    = (const float*)d_in[12 + o];
    const float* prb1    = (const float*)d_in[13 + o];
    const float* prW2    = (const float*)d_in[14 + o];
    const float* prb2    = (const float*)d_in[15 + o];
    const float* prW3    = (const float*)d_in[16 + o];
    const float* prb3    = (const float*)d_in[17 + o];
    float* out = (float*)d_out;

    int n = in_sizes[1 + o] / E;   // total ops (102400)

    k_setup<<<1, 1024>>>(num_ops, z, opW1, opb1, prW1, prb1);
    k_pre<<<16, 128>>>(opW1, prW1, y);
    k_ops<<<(n + 255) / 256, 128>>>(x, opW1, opW2, opb2, opW3, opb3, op_msk, n);
    k_sum<<<400, 256>>>(n);
    k_norm<<<(n + 1023) / 1024, 1024>>>(out, n);
    k_prlvl<<<ND, NW>>>(prW1, prW2, prb2, prW3, prb3, pr_msk, out, n);
}

// round 6
// speedup vs baseline: 2.3878x; 1.1334x over previous
#include <cuda_runtime.h>

#define TOTAL_OPS 102400
#define ND 1024
#define NW 64
#define E 256
#define H1N 32
#define H2N 16

// ---------------- device scratch (no allocations allowed) ----------------
__device__ float    g_logits[TOTAL_OPS];
__device__ int      g_cum[ND];          // inclusive cumsum of num_ops
__device__ float    g_yw_op[ND * H1N];
__device__ float    g_yw_pr[ND * H1N];
__device__ float    g_zc_op[H1N];       // b1 + z@W1z (op)
__device__ float    g_zc_pr[H1N];       // b1 + z@W1z (pr)
__device__ unsigned g_maxbits;
__device__ float    g_sum;
__device__ unsigned g_cnt;

typedef unsigned long long ull;

// ---------------- packed fp32x2 helpers (sm_103a FFMA2 path) ----------------
__device__ __forceinline__ ull fma2(ull a, ull b, ull c) {
    ull d;
    asm("fma.rn.f32x2 %0, %1, %2, %3;" : "=l"(d) : "l"(a), "l"(b), "l"(c));
    return d;
}
__device__ __forceinline__ ull splat2(float x) {
    ull d;
    asm("mov.b64 %0, {%1, %1};" : "=l"(d) : "f"(x));
    return d;
}
__device__ __forceinline__ void unpack2(ull v, float& lo, float& hi) {
    asm("mov.b64 {%0, %1}, %2;" : "=f"(lo), "=f"(hi) : "l"(v));
}

// monotone float -> unsigned map for atomicMax
__device__ __forceinline__ unsigned encf(float f) {
    unsigned b = __float_as_uint(f);
    return (b & 0x80000000u) ? ~b : (b | 0x80000000u);
}
__device__ __forceinline__ float decf(unsigned u) {
    return (u & 0x80000000u) ? __uint_as_float(u & 0x7FFFFFFFu)
                             : __uint_as_float(~u);
}

// ---------------- K0: scan + z-projections + resets (1 block) ----------------
__global__ void __launch_bounds__(1024) k_setup(
    const int* __restrict__ num_ops,
    const float* __restrict__ z,
    const float* __restrict__ opW1, const float* __restrict__ opb1,
    const float* __restrict__ prW1, const float* __restrict__ prb1)
{
    __shared__ int s[ND];
    int t = threadIdx.x;

    // --- inclusive scan of num_ops (1024 wide) ---
    s[t] = num_ops[t];
    __syncthreads();
    for (int off = 1; off < ND; off <<= 1) {
        int v = (t >= off) ? s[t - off] : 0;
        __syncthreads();
        s[t] += v;
        __syncthreads();
    }
    g_cum[t] = s[t];

    // --- z-projections: 64 outputs x 16 threads x 16 k-terms ---
    int table = t >> 9;                 // 0 = op, 1 = pr
    int j     = (t >> 4) & 31;          // output index
    int sub   = t & 15;                 // k sub-chunk
    const float* W1 = table ? prW1 : opW1;
    const float* b1 = table ? prb1 : opb1;
    int offZ = table ? (E + 1) : (2 * E);
    float c = 0.f;
    int k0 = sub * 16;
#pragma unroll 4
    for (int k = k0; k < k0 + 16; k++)
        c += z[k] * W1[(offZ + k) * H1N + j];
#pragma unroll
    for (int o = 8; o > 0; o >>= 1)
        c += __shfl_xor_sync(0xffffffffu, c, o);   // within 16-lane group
    if (sub == 0) {
        float v = c + b1[j];
        if (table) g_zc_pr[j] = v; else g_zc_op[j] = v;
    }

    if (t == 0) { g_maxbits = 0u; g_sum = 0.f; g_cnt = 0u; }
}

// ---------------- K1: per-dag tables yW = y@W1y + zc (2 threads/dag) ---------
__global__ void __launch_bounds__(128) k_pre(
    const float* __restrict__ opW1, const float* __restrict__ prW1,
    const float* __restrict__ y)
{
    __shared__ __align__(16) float sW[E * H1N];    // 32 KB y-part of W1
    __shared__ float szc[H1N];
    int b = blockIdx.x;
    int table = b >> 4;                 // blocks 0-15 op, 16-31 pr
    int d0 = (b & 15) * 64;
    const float* W1 = table ? prW1 : opW1;
    int f4off = table ? (1 * H1N / 4) : (E * H1N / 4);   // float4 offset of y-part
    const float* zc = table ? g_zc_pr : g_zc_op;
    float* outT = table ? g_yw_pr : g_yw_op;

    int t = threadIdx.x;
    const float4* gW4 = (const float4*)W1;
    float4* sW4 = (float4*)sW;
#pragma unroll
    for (int i = 0; i < 16; i++) sW4[i * 128 + t] = gW4[f4off + i * 128 + t];
    if (t < H1N) szc[t] = zc[t];
    __syncthreads();

    int d = d0 + (t >> 1);              // 64 dags per block, 2 threads each
    int half = t & 1;                   // K half: [half*128, half*128+128)
    ull acc[16];
#pragma unroll
    for (int q = 0; q < 16; q++) acc[q] = 0ull;
    const float4* yr = (const float4*)&y[d * E];
    const ulonglong2* sWu = (const ulonglong2*)sW;

    int kc0 = half * 32;                // float4 index range [kc0, kc0+32)
    float4 va = yr[kc0];
    for (int kc = 0; kc < 32; kc++) {
        float4 pa = yr[kc0 + ((kc + 1) & 31)];
        float f[4] = {va.x, va.y, va.z, va.w};
#pragma unroll
        for (int kk = 0; kk < 4; kk++) {
            ull xd = splat2(f[kk]);
            const ulonglong2* w = &sWu[((kc0 + kc) * 4 + kk) * 8];
#pragma unroll
            for (int q = 0; q < 8; q++) {
                ulonglong2 wv = w[q];
                acc[2 * q]     = fma2(xd, wv.x, acc[2 * q]);
                acc[2 * q + 1] = fma2(xd, wv.y, acc[2 * q + 1]);
            }
        }
        va = pa;
    }
    float h[H1N];
#pragma unroll
    for (int q = 0; q < 16; q++) unpack2(acc[q], h[2 * q], h[2 * q + 1]);
#pragma unroll
    for (int j = 0; j < H1N; j++)
        h[j] += __shfl_xor_sync(0xffffffffu, h[j], 1);   // combine K halves
    if (half == 0) {
#pragma unroll
        for (int j = 0; j < H1N; j++) outT[d * H1N + j] = h[j] + szc[j];
    }
}

// ---------------- K2: prlvl branch, fused per-dag softmax ----------------
__global__ void __launch_bounds__(NW) k_prlvl(
    const float* __restrict__ prW1, const float* __restrict__ prW2,
    const float* __restrict__ prb2, const float* __restrict__ prW3,
    const float* __restrict__ prb3, const float* __restrict__ msk,
    float* __restrict__ out, int nops)
{
    __shared__ __align__(16) float sW2[H1N * H2N];
    __shared__ float sb2[H2N], sW3[H2N];
    __shared__ float sb3;
    __shared__ float sw1r0[H1N], sbase[H1N];
    __shared__ float red[2];

    int d = blockIdx.x, w = threadIdx.x;
    for (int i = w; i < H1N * H2N; i += NW) sW2[i] = prW2[i];
    if (w < H2N) { sb2[w] = prb2[w]; sW3[w] = prW3[w]; }
    if (w == 0) sb3 = prb3[0];
    if (w < H1N) { sw1r0[w] = prW1[w]; sbase[w] = g_yw_pr[d * H1N + w]; }
    __syncthreads();

    float limit = (float)(w + 1);
    float h2[H2N];
#pragma unroll
    for (int j2 = 0; j2 < H2N; j2++) h2[j2] = sb2[j2];
#pragma unroll
    for (int j = 0; j < H1N; j++) {
        float v = fmaxf(sbase[j] + limit * sw1r0[j], 0.f);
        const float4* w2 = (const float4*)&sW2[j * H2N];
#pragma unroll
        for (int q2 = 0; q2 < 4; q2++) {
            float4 wv = w2[q2];
            h2[4 * q2 + 0] += v * wv.x;
            h2[4 * q2 + 1] += v * wv.y;
            h2[4 * q2 + 2] += v * wv.z;
            h2[4 * q2 + 3] += v * wv.w;
        }
    }
    float logit = sb3;
#pragma unroll
    for (int j2 = 0; j2 < H2N; j2++) logit += fmaxf(h2[j2], 0.f) * sW3[j2];
    logit -= (1.f - msk[d * NW + w]) * 1000.f;

    float m = logit;
#pragma unroll
    for (int o = 16; o > 0; o >>= 1) m = fmaxf(m, __shfl_xor_sync(0xffffffffu, m, o));
    if ((w & 31) == 0) red[w >> 5] = m;
    __syncthreads();
    m = fmaxf(red[0], red[1]);
    float e = expf(logit - m);
    float s = e;
#pragma unroll
    for (int o = 16; o > 0; o >>= 1) s += __shfl_xor_sync(0xffffffffu, s, o);
    __syncthreads();
    if ((w & 31) == 0) red[w >> 5] = s;
    __syncthreads();
    s = red[0] + red[1];
    out[nops + d * NW + w] = e / s;
}

// ---------------- K3: op MLP -> logits + block max (2 rows/thread) -----------
__global__ void __launch_bounds__(128) k_ops(
    const float* __restrict__ x, const float* __restrict__ opW1,
    const float* __restrict__ opW2, const float* __restrict__ opb2,
    const float* __restrict__ opW3, const float* __restrict__ opb3,
    const float* __restrict__ op_msk, int nrows)
{
    __shared__ __align__(16) float sW[E * H1N];    // 32 KB W1 x-part
    __shared__ int sCum[ND];                       // 4 KB cumsum
    __shared__ __align__(16) float sW2[H1N * H2N];
    __shared__ float sb2[H2N], sW3[H2N];
    __shared__ float sb3;
    __shared__ float wmax[4];

    int t = threadIdx.x;
    const float4* gW4 = (const float4*)opW1;       // rows 0..255 = x-part
    float4* sW4 = (float4*)sW;
#pragma unroll
    for (int i = 0; i < 16; i++) sW4[i * 128 + t] = gW4[i * 128 + t];
#pragma unroll
    for (int i = 0; i < 8; i++) sCum[i * 128 + t] = g_cum[i * 128 + t];
    for (int i = t; i < H1N * H2N; i += 128) sW2[i] = opW2[i];
    if (t < H2N) { sb2[t] = opb2[t]; sW3[t] = opW3[t]; }
    if (t == 0) sb3 = opb3[0];
    __syncthreads();

    int row0 = blockIdx.x * 256;
    int ia = row0 + t, ib = row0 + 128 + t;
    const float4* xa = (const float4*)&x[(size_t)min(ia, nrows - 1) * E];
    const float4* xb = (const float4*)&x[(size_t)min(ib, nrows - 1) * E];

    ull accA[16], accB[16];
#pragma unroll
    for (int q = 0; q < 16; q++) { accA[q] = 0ull; accB[q] = 0ull; }
    const ulonglong2* sWu = (const ulonglong2*)sW;

    // software pipeline: prefetch kc+1 while computing kc
    float4 va = xa[0];
    float4 vb = xb[0];
    for (int kc = 0; kc < 64; kc++) {
        float4 pa = xa[(kc + 1) & 63];
        float4 pb = xb[(kc + 1) & 63];
        float fa[4] = {va.x, va.y, va.z, va.w};
        float fb[4] = {vb.x, vb.y, vb.z, vb.w};
#pragma unroll
        for (int kk = 0; kk < 4; kk++) {
            ull da = splat2(fa[kk]);
            ull db = splat2(fb[kk]);
            const ulonglong2* w = &sWu[(kc * 4 + kk) * 8];
#pragma unroll
            for (int q = 0; q < 8; q++) {
                ulonglong2 wv = w[q];
                accA[2 * q]     = fma2(da, wv.x, accA[2 * q]);
                accA[2 * q + 1] = fma2(da, wv.y, accA[2 * q + 1]);
                accB[2 * q]     = fma2(db, wv.x, accB[2 * q]);
                accB[2 * q + 1] = fma2(db, wv.y, accB[2 * q + 1]);
            }
        }
        va = pa; vb = pb;
    }

    float m = -3.402823466e38f;
#pragma unroll
    for (int r = 0; r < 2; r++) {
        int i = r ? ib : ia;
        ull* acc = r ? accB : accA;
        if (i < nrows) {
            float h1[H1N];
#pragma unroll
            for (int q = 0; q < 16; q++) unpack2(acc[q], h1[2 * q], h1[2 * q + 1]);
            // dag = max{ d : exclusive_cum[d] <= i }
            int d = 0;
#pragma unroll
            for (int s = 512; s > 0; s >>= 1)
                if (d + s <= ND - 1 && sCum[d + s - 1] <= i) d += s;
            const float4* bw = (const float4*)&g_yw_op[d * H1N];
#pragma unroll
            for (int q = 0; q < 8; q++) {
                float4 b = bw[q];
                h1[4 * q + 0] = fmaxf(h1[4 * q + 0] + b.x, 0.f);
                h1[4 * q + 1] = fmaxf(h1[4 * q + 1] + b.y, 0.f);
                h1[4 * q + 2] = fmaxf(h1[4 * q + 2] + b.z, 0.f);
                h1[4 * q + 3] = fmaxf(h1[4 * q + 3] + b.w, 0.f);
            }
            float h2[H2N];
#pragma unroll
            for (int j2 = 0; j2 < H2N; j2++) h2[j2] = sb2[j2];
#pragma unroll
            for (int j = 0; j < H1N; j++) {
                float v = h1[j];
                const float4* w2 = (const float4*)&sW2[j * H2N];
#pragma unroll
                for (int q2 = 0; q2 < 4; q2++) {
                    float4 wv = w2[q2];
                    h2[4 * q2 + 0] += v * wv.x;
                    h2[4 * q2 + 1] += v * wv.y;
                    h2[4 * q2 + 2] += v * wv.z;
                    h2[4 * q2 + 3] += v * wv.w;
                }
            }
            float logit = sb3;
#pragma unroll
            for (int j2 = 0; j2 < H2N; j2++) logit += fmaxf(h2[j2], 0.f) * sW3[j2];
            logit -= (1.f - op_msk[i]) * 1000.f;
            g_logits[i] = logit;
            m = fmaxf(m, logit);
        }
    }
#pragma unroll
    for (int o = 16; o > 0; o >>= 1) m = fmaxf(m, __shfl_xor_sync(0xffffffffu, m, o));
    if ((t & 31) == 0) wmax[t >> 5] = m;
    __syncthreads();
    if (t == 0) {
        float bm = fmaxf(fmaxf(wmax[0], wmax[1]), fmaxf(wmax[2], wmax[3]));
        atomicMax(&g_maxbits, encf(bm));
    }
}

// ---------------- K4: fused exp + global sum + normalize (spin barrier) ------
__global__ void __launch_bounds__(256) k_sum_norm(float* __restrict__ out, int n) {
    __shared__ float sp[8];
    __shared__ float sInv;
    int t = threadIdx.x;
    int i = blockIdx.x * 256 + t;
    float gm = decf(g_maxbits);
    float e = 0.f;
    if (i < n) e = expf(g_logits[i] - gm);

    float s = e;
#pragma unroll
    for (int o = 16; o > 0; o >>= 1) s += __shfl_xor_sync(0xffffffffu, s, o);
    if ((t & 31) == 0) sp[t >> 5] = s;
    __syncthreads();
    if (t == 0) {
        float bs = 0.f;
#pragma unroll
        for (int w = 0; w < 8; w++) bs += sp[w];
        atomicAdd(&g_sum, bs);
        __threadfence();
        atomicAdd(&g_cnt, 1u);
        // spin until all blocks have contributed
        volatile unsigned* vc = &g_cnt;
        while (*vc < gridDim.x) { }
        __threadfence();
        sInv = 1.f / *((volatile float*)&g_sum);
    }
    __syncthreads();
    if (i < n) out[i] = e * sInv;
}

// ---------------- launcher ----------------
extern "C" void kernel_launch(void* const* d_in, const int* in_sizes, int n_in,
                              void* d_out, int out_size) {
    int o = (n_in >= 20) ? 2 : 0;
    const int*   num_ops = (const int*)d_in[0];
    const float* x       = (const float*)d_in[1 + o];
    const float* y       = (const float*)d_in[2 + o];
    const float* z       = (const float*)d_in[3 + o];
    const float* op_msk  = (const float*)d_in[4 + o];
    const float* pr_msk  = (const float*)d_in[5 + o];
    const float* opW1    = (const float*)d_in[6 + o];
    const float* opb1    = (const float*)d_in[7 + o];
    const float* opW2    = (const float*)d_in[8 + o];
    const float* opb2    = (const float*)d_in[9 + o];
    const float* opW3    = (const float*)d_in[10 + o];
    const float* opb3    = (const float*)d_in[11 + o];
    const float* prW1    = (const float*)d_in[12 + o];
    const float* prb1    = (const float*)d_in[13 + o];
    const float* prW2    = (const float*)d_in[14 + o];
    const float* prb2    = (const float*)d_in[15 + o];
    const float* prW3    = (const float*)d_in[16 + o];
    const float* prb3    = (const float*)d_in[17 + o];
    float* out = (float*)d_out;

    int n = in_sizes[1 + o] / E;   // total ops (102400)

    k_setup<<<1, 1024>>>(num_ops, z, opW1, opb1, prW1, prb1);
    k_pre<<<32, 128>>>(opW1, prW1, y);
    k_prlvl<<<ND, NW>>>(prW1, prW2, prb2, prW3, prb3, pr_msk, out, n);
    k_ops<<<(n + 255) / 256, 128>>>(x, opW1, opW2, opb2, opW3, opb3, op_msk, n);
    k_sum_norm<<<(n + 255) / 256, 256>>>(out, n);
}